// round 16
// baseline (speedup 1.0000x reference)
#include <cuda_runtime.h>
#include <cuda_bf16.h>
#include <stdint.h>

#define NN 96
#define DD 64
#define CC 30

// Scratch (__device__ globals; no allocation allowed)
__device__ float    g_mat[NN * NN];
__device__ unsigned g_smask[NN * 3];
__device__ unsigned g_dmask[NN * 3];
__device__ float    g_rnum[NN], g_rq[NN];
__device__ unsigned g_cmask[NN * NN * 4];   // 96-bit mask per (i,p), stride 4 words

// ---------------------------------------------------------------------------
// zeroK: 4608 uniform blocks x 256. Depends on NOTHING. Triggers the PDL
// chain at entry so prepA starts immediately. Zero prefixes (k <= j) of slab
// pair (j1 = p, j2 = 95-p): (j1+1)+(j2+1) = 97 rows = 2328 float4 -> uniform.
// ---------------------------------------------------------------------------
__global__ __launch_bounds__(256) void zeroK(float4* __restrict__ out) {
#if __CUDA_ARCH__ >= 900
    cudaTriggerProgrammaticLaunchCompletion();   // release prepA NOW
#endif
    const int tid = threadIdx.x;
    const int zid = blockIdx.x;              // 0..4607
    const int i   = zid / 48;
    const int p   = zid - i * 48;            // 0..47
    const int j1  = p;
    const int j2  = NN - 1 - p;
    const int len1 = (j1 + 1) * 24;
    const int len2 = (j2 + 1) * 24;
    float4* o1 = out + ((size_t)i * NN + j1) * 2304;
    float4* o2 = out + ((size_t)i * NN + j2) * 2304;
    const float4 z4 = make_float4(0.f, 0.f, 0.f, 0.f);
    const int total = len1 + len2;           // 2328 always
    for (int pos = tid; pos < total; pos += 256) {
        int p2 = pos - len1;
        if (p2 < 0) __stcs(o1 + pos, z4);
        else        __stcs(o2 + p2,  z4);
    }
}

// ---------------------------------------------------------------------------
// prepA: 96 blocks x 512 (verbatim R15). Block i owns anchor i.
// ---------------------------------------------------------------------------
__global__ __launch_bounds__(512) void prepA(const float* __restrict__ logits,
                                             const float* __restrict__ labels) {
    __shared__ float    sx[NN * 65];
    __shared__ float    slab[NN * CC];
    __shared__ float    rn[NN];
    __shared__ float    srow[NN];
    __shared__ unsigned sm[3], dm[3];

    const int tid  = threadIdx.x;
    const int ianc = blockIdx.x;
    const int warp = tid >> 5, lane = tid & 31;

    #pragma unroll
    for (int it = 0; it < 12; it++) {                 // 6144 = 12*512
        int t = it * 512 + tid;
        sx[(t >> 6) * 65 + (t & 63)] = logits[t];
    }
    #pragma unroll
    for (int it = 0; it < 6; it++) {                  // 2880 = 96*30
        int t = it * 512 + tid;
        if (t < NN * CC) slab[t] = labels[t];
    }
    __syncthreads();

    float acc = 0.f;
    if (tid < NN) {
        float sc = 0.f;
        #pragma unroll
        for (int d = 0; d < DD; d++) {
            float vi = sx[ianc * 65 + d];
            float vt = sx[tid  * 65 + d];
            sc  += vt * vt;                           // == old norm order
            acc += vi * vt;                           // == old dot order
        }
        rn[tid] = rsqrtf(sc);
    } else if (warp == 3) {
        #pragma unroll
        for (int wd = 0; wd < 3; wd++) {
            int j = wd * 32 + lane;
            float a = 0.f;
            #pragma unroll
            for (int cc = 0; cc < CC; cc++) a += slab[ianc * CC + cc] * slab[j * CC + cc];
            bool same_raw = a > 0.f;
            unsigned sb = __ballot_sync(0xffffffffu, same_raw && (j != ianc));
            unsigned db = __ballot_sync(0xffffffffu, !same_raw);
            if (lane == 0) {
                sm[wd] = sb;  dm[wd] = db;
                g_smask[ianc * 3 + wd] = sb;
                g_dmask[ianc * 3 + wd] = db;
            }
        }
    }
    __syncthreads();

    if (tid < NN) {
        float v = -acc * rn[ianc] * rn[tid];
        srow[tid] = v;
        g_mat[ianc * NN + tid] = v;
    }
    __syncthreads();

    if (warp == 0) {
        float S = 0.f, ds = 0.f, ms = 0.f, md = 0.f;
        #pragma unroll
        for (int jj = 0; jj < 3; jj++) {
            float mv = srow[jj * 32 + lane];
            if ((sm[jj] >> lane) & 1u) { S += 1.f; ms += mv; }
            if ((dm[jj] >> lane) & 1u) { ds += 1.f; md += mv; }
        }
        #pragma unroll
        for (int o = 16; o; o >>= 1) {
            S  += __shfl_xor_sync(0xffffffffu, S,  o);
            ds += __shfl_xor_sync(0xffffffffu, ds, o);
            ms += __shfl_xor_sync(0xffffffffu, ms, o);
            md += __shfl_xor_sync(0xffffffffu, md, o);
        }
        if (lane == 0) {
            g_rnum[ianc] = (S - 1.f) * (S * md - ms * ds);
            g_rq[ianc]   = 0.5f * S * (S - 1.f) * ds;
        }
    }
}

// ---------------------------------------------------------------------------
// prepB: 96 blocks x 256 (verbatim R14). Redundant serial eps reduce
// (identical i-ascending order -> deterministic), then cmask ballots.
// ---------------------------------------------------------------------------
__global__ __launch_bounds__(256) void prepB() {
    __shared__ float    srow[NN];
    __shared__ unsigned sm[3], dm[3];
    __shared__ float    s_eps;

    const int tid  = threadIdx.x;
    const int ianc = blockIdx.x;
    const int warp = tid >> 5, lane = tid & 31;

    if (tid < NN) srow[tid] = g_mat[ianc * NN + tid];
    if (tid >= NN && tid < NN + 3) {
        sm[tid - NN] = g_smask[ianc * 3 + (tid - NN)];
        dm[tid - NN] = g_dmask[ianc * 3 + (tid - NN)];
    }
    if (tid == 128) {
        float num = 0.f, q = 0.f;
        for (int i = 0; i < NN; i++) { num += g_rnum[i]; q += g_rq[i]; }
        float mean_delta = num / fmaxf(2.f * q, 1.f);
        s_eps = fmaxf(mean_delta * 0.5f, 0.f);   // relu(mean_delta / K_DELTA)
    }
    __syncthreads();
    const float eps = s_eps;

    for (int p = warp; p < NN; p += 8) {
        unsigned sp = (sm[p >> 5] >> (p & 31)) & 1u;
        float matp = srow[p];
        #pragma unroll
        for (int wd = 0; wd < 3; wd++) {
            float m = srow[wd * 32 + lane] - matp;
            bool cc = sp && (((dm[wd] >> lane) & 1u) != 0u) && (m > 0.f) && (m <= eps);
            unsigned b = __ballot_sync(0xffffffffu, cc);
            if (lane == 0) g_cmask[(ianc * NN + p) * 4 + wd] = b;
        }
    }
}

// ---------------------------------------------------------------------------
// dataK: 9216 blocks x 256 (verbatim R7 k2_write). Writes ONLY the k > j
// suffix of slab (i,j) — disjoint from zeroK's bytes, so overlapping
// execution with zeroK's tail is safe.
// ---------------------------------------------------------------------------
__global__ __launch_bounds__(256) void dataK(float4* __restrict__ out) {
    __shared__ unsigned sw[NN * 3];
    const int r2 = blockIdx.x;           // i*96 + j
    const int j  = r2 % NN;
    if (j == NN - 1) return;             // empty suffix
    const int ibase = r2 - j;            // i*96
    const int tid = threadIdx.x;

    for (int t = tid; t < NN * 3; t += 256) {
        int k  = t / 3;
        int wd = t - k * 3;
        unsigned v = 0u;
        if (k > j)
            v = g_cmask[(r2 << 2) + wd] & g_cmask[((ibase + k) << 2) + wd];
        sw[t] = v;
    }
    __syncthreads();

    float4* o = out + (size_t)r2 * 2304 + (j + 1) * 24;
    const int len = (NN - 1 - j) * 24;
    const unsigned ONEF = 0x3f800000u;
    for (int pos = tid; pos < len; pos += 256) {
        int q  = pos / 24;
        int r  = pos - q * 24;
        int k  = j + 1 + q;
        unsigned w = sw[k * 3 + (r >> 3)];
        unsigned b = w >> ((r & 7) * 4);
        float4 v;
        v.x = __uint_as_float(ONEF & (0u - (b & 1u)));
        v.y = __uint_as_float(ONEF & (0u - ((b >> 1) & 1u)));
        v.z = __uint_as_float(ONEF & (0u - ((b >> 2) & 1u)));
        v.w = __uint_as_float(ONEF & (0u - ((b >> 3) & 1u)));
        __stcs(o + pos, v);
    }
}

// ---------------------------------------------------------------------------
// PDL chain: zeroK (trigger@entry) -> prepA -> prepB -> dataK. No kernel
// ever waits on the device; overlap comes from programmatic early launch.
// ---------------------------------------------------------------------------
static void launch_pdl(void* fn, dim3 grid, dim3 block, void** args) {
    cudaLaunchConfig_t cfg = {};
    cfg.gridDim  = grid;
    cfg.blockDim = block;
    cfg.dynamicSmemBytes = 0;
    cfg.stream = 0;
    cudaLaunchAttribute attr[1];
    attr[0].id = cudaLaunchAttributeProgrammaticStreamSerialization;
    attr[0].val.programmaticStreamSerializationAllowed = 1;
    cfg.attrs = attr;
    cfg.numAttrs = 1;
    cudaLaunchKernelExC(&cfg, fn, args);
}

extern "C" void kernel_launch(void* const* d_in, const int* in_sizes, int n_in,
                              void* d_out, int out_size) {
    const float* logits = (const float*)d_in[0];   // [96,64]
    const float* labels = (const float*)d_in[1];   // [96,30]
    float4* out = (float4*)d_out;

    zeroK<<<NN * 48, 256>>>(out);                  // triggers at entry

    void* argsA[] = { (void*)&logits, (void*)&labels };
    launch_pdl((void*)prepA, dim3(NN), dim3(512), argsA);

    void* argsB[] = { (void*)0 };                  // prepB takes no args
    launch_pdl((void*)prepB, dim3(NN), dim3(256), (void**)argsB);

    void* argsD[] = { (void*)&out };
    launch_pdl((void*)dataK, dim3(NN * NN), dim3(256), argsD);
}